// round 1
// baseline (speedup 1.0000x reference)
#include <cuda_runtime.h>
#include <cuda_bf16.h>
#include <cstdint>

#define NN 50000
#define DD 64
#define HH 4
#define RR 4
#define EE 800000
#define HD 256     // H*D
#define RHD 1024   // R*H*D

// ---------------- scratch (static device globals; no allocation) ----------------
__device__ __nv_bfloat16 g_Q[(size_t)RR * NN * HD];   // 102.4 MB
__device__ __nv_bfloat16 g_K[(size_t)RR * NN * HD];   // 102.4 MB
__device__ float         g_V[(size_t)RR * NN * HD];   // 204.8 MB
__device__ float         g_comb[(size_t)NN * RHD];    // 204.8 MB
__device__ float         g_esc[(size_t)RR * EE * HH]; // 51.2 MB
__device__ int           g_cnt[RR * NN];
__device__ int           g_off[RR * (NN + 1)];
__device__ int           g_cur[RR * NN];
__device__ int           g_csr[(size_t)RR * EE];      // 12.8 MB

// ---------------- helpers ----------------
__device__ __forceinline__ void ld_bf16x8(const __nv_bfloat16* p, float* f) {
    uint4 u = *reinterpret_cast<const uint4*>(p);
    unsigned w[4] = {u.x, u.y, u.z, u.w};
#pragma unroll
    for (int i = 0; i < 4; i++) {
        float2 t = __bfloat1622float2(*reinterpret_cast<__nv_bfloat162*>(&w[i]));
        f[2 * i] = t.x;
        f[2 * i + 1] = t.y;
    }
}

// ---------------- 0: zero histogram ----------------
__global__ void zero_cnt_kernel() {
    int i = blockIdx.x * blockDim.x + threadIdx.x;
    if (i < RR * NN) g_cnt[i] = 0;
}

// ---------------- 1: QKV projections  X[N,64] @ W[64,256] + b  ----------------
// grid: (ceil(N/128), 2 col-halves, 12 = R*3 matrices), 256 threads, 8x8/thread
__global__ void __launch_bounds__(256) qkv_gemm(
    const float* __restrict__ X,
    const float* __restrict__ Wq, const float* __restrict__ bq,
    const float* __restrict__ Wk, const float* __restrict__ bk,
    const float* __restrict__ Wv, const float* __restrict__ bv) {
    int m = blockIdx.z;
    int r = m / 3, t = m % 3;
    const float* W    = (t == 0 ? Wq : t == 1 ? Wk : Wv) + (size_t)r * DD * HD;
    const float* bias = (t == 0 ? bq : t == 1 ? bk : bv) + (size_t)r * HD;
    int row0 = blockIdx.x * 128;
    int col0 = blockIdx.y * 128;

    __shared__ float As[32][128];  // transposed: As[k][row]
    __shared__ float Bs[32][128];  // Bs[k][col]

    int tid = threadIdx.x;
    int tx = tid & 15, ty = tid >> 4;
    float acc[8][8] = {};

    for (int k0 = 0; k0 < DD; k0 += 32) {
#pragma unroll
        for (int i = tid * 4; i < 128 * 32; i += 1024) {
            int rr = i >> 5, kk = i & 31;
            int row = row0 + rr;
            float4 v = make_float4(0.f, 0.f, 0.f, 0.f);
            if (row < NN)
                v = *reinterpret_cast<const float4*>(X + (size_t)row * DD + k0 + kk);
            As[kk + 0][rr] = v.x; As[kk + 1][rr] = v.y;
            As[kk + 2][rr] = v.z; As[kk + 3][rr] = v.w;
        }
#pragma unroll
        for (int i = tid * 4; i < 32 * 128; i += 1024) {
            int kk = i >> 7, cc = i & 127;
            *reinterpret_cast<float4*>(&Bs[kk][cc]) =
                *reinterpret_cast<const float4*>(W + (size_t)(k0 + kk) * HD + col0 + cc);
        }
        __syncthreads();
#pragma unroll
        for (int kk = 0; kk < 32; kk++) {
            float a[8], b[8];
            *reinterpret_cast<float4*>(a)     = *reinterpret_cast<const float4*>(&As[kk][ty * 8]);
            *reinterpret_cast<float4*>(a + 4) = *reinterpret_cast<const float4*>(&As[kk][ty * 8 + 4]);
            *reinterpret_cast<float4*>(b)     = *reinterpret_cast<const float4*>(&Bs[kk][tx * 8]);
            *reinterpret_cast<float4*>(b + 4) = *reinterpret_cast<const float4*>(&Bs[kk][tx * 8 + 4]);
#pragma unroll
            for (int i = 0; i < 8; i++)
#pragma unroll
                for (int j = 0; j < 8; j++) acc[i][j] += a[i] * b[j];
        }
        __syncthreads();
    }

    float bsv[8];
#pragma unroll
    for (int j = 0; j < 8; j++) bsv[j] = bias[col0 + tx * 8 + j];

#pragma unroll
    for (int i = 0; i < 8; i++) {
        int row = row0 + ty * 8 + i;
        if (row >= NN) continue;
        size_t o = ((size_t)r * NN + row) * HD + col0 + tx * 8;
        if (t == 2) {
            float4 lo = make_float4(acc[i][0] + bsv[0], acc[i][1] + bsv[1],
                                    acc[i][2] + bsv[2], acc[i][3] + bsv[3]);
            float4 hi = make_float4(acc[i][4] + bsv[4], acc[i][5] + bsv[5],
                                    acc[i][6] + bsv[6], acc[i][7] + bsv[7]);
            *reinterpret_cast<float4*>(g_V + o) = lo;
            *reinterpret_cast<float4*>(g_V + o + 4) = hi;
        } else {
            __nv_bfloat16* dst = (t == 0 ? g_Q : g_K) + o;
            __nv_bfloat162 p0 = __floats2bfloat162_rn(acc[i][0] + bsv[0], acc[i][1] + bsv[1]);
            __nv_bfloat162 p1 = __floats2bfloat162_rn(acc[i][2] + bsv[2], acc[i][3] + bsv[3]);
            __nv_bfloat162 p2 = __floats2bfloat162_rn(acc[i][4] + bsv[4], acc[i][5] + bsv[5]);
            __nv_bfloat162 p3 = __floats2bfloat162_rn(acc[i][6] + bsv[6], acc[i][7] + bsv[7]);
            uint4 u;
            u.x = *reinterpret_cast<unsigned*>(&p0);
            u.y = *reinterpret_cast<unsigned*>(&p1);
            u.z = *reinterpret_cast<unsigned*>(&p2);
            u.w = *reinterpret_cast<unsigned*>(&p3);
            *reinterpret_cast<uint4*>(dst) = u;
        }
    }
}

// ---------------- 2: histogram of edges per src ----------------
__global__ void hist_kernel(const int* __restrict__ esrc) {
    int r = blockIdx.y;
    int i = blockIdx.x * blockDim.x + threadIdx.x;
    if (i < EE) atomicAdd(&g_cnt[r * NN + esrc[(size_t)r * EE + i]], 1);
}

// ---------------- 3: exclusive scan per relation (one block each) ----------------
__global__ void scan_kernel() {
    int r = blockIdx.x;
    int t = threadIdx.x;
    int lane = t & 31, wid = t >> 5;
    __shared__ int wsum[32];
    __shared__ int carry_s;
    if (t == 0) carry_s = 0;
    __syncthreads();
    for (int base = 0; base < NN; base += 1024) {
        int i = base + t;
        int v = (i < NN) ? g_cnt[r * NN + i] : 0;
        int x = v;
#pragma unroll
        for (int o = 1; o < 32; o <<= 1) {
            int y = __shfl_up_sync(0xffffffffu, x, o);
            if (lane >= o) x += y;
        }
        if (lane == 31) wsum[wid] = x;
        __syncthreads();
        if (wid == 0) {
            int w = wsum[lane];
#pragma unroll
            for (int o = 1; o < 32; o <<= 1) {
                int y = __shfl_up_sync(0xffffffffu, w, o);
                if (lane >= o) w += y;
            }
            wsum[lane] = w;
        }
        __syncthreads();
        int excl = x - v + carry_s + (wid > 0 ? wsum[wid - 1] : 0);
        if (i < NN) {
            g_off[r * (NN + 1) + i] = excl;
            g_cur[r * NN + i] = excl;
        }
        __syncthreads();
        if (t == 0) carry_s += wsum[31];
        __syncthreads();
    }
    if (t == 0) g_off[r * (NN + 1) + NN] = carry_s;
}

// ---------------- 4: scatter edges into CSR ----------------
__global__ void scatter_kernel(const int* __restrict__ esrc, const int* __restrict__ etgt) {
    int r = blockIdx.y;
    int i = blockIdx.x * blockDim.x + threadIdx.x;
    if (i < EE) {
        int s = esrc[(size_t)r * EE + i];
        int pos = atomicAdd(&g_cur[r * NN + s], 1);
        g_csr[(size_t)r * EE + pos] = etgt[(size_t)r * EE + i];
    }
}

// ---------------- 5: fused edge-softmax + aggregation, one warp per (r,node) ----
// Lane layout: head h = lane>>3, sub = lane&7; lane owns cols h*64 + sub*8 .. +7.
__global__ void __launch_bounds__(256) attn_kernel(const float* __restrict__ infl,
                                                   const float* __restrict__ signw) {
    int r = blockIdx.y;
    int node = blockIdx.x * 8 + (threadIdx.x >> 5);
    if (node >= NN) return;
    int lane = threadIdx.x & 31;
    int h = lane >> 3, sub = lane & 7;

    float q[8];
    ld_bf16x8(g_Q + ((size_t)r * NN + node) * HD + h * 64 + sub * 8, q);
    float fh = infl[node] * signw[h * RR + r] * 0.125f;  // 1/sqrt(64) = 0.125

    int beg = g_off[r * (NN + 1) + node];
    int end = g_off[r * (NN + 1) + node + 1];

    // pass A: scores -> exp, store e, accumulate softmax denominator
    float ssum = 0.f;
    for (int p = beg; p < end; p++) {
        int tgt = g_csr[(size_t)r * EE + p];
        float k[8];
        ld_bf16x8(g_K + ((size_t)r * NN + tgt) * HD + h * 64 + sub * 8, k);
        float d = q[0] * k[0] + q[1] * k[1] + q[2] * k[2] + q[3] * k[3] +
                  q[4] * k[4] + q[5] * k[5] + q[6] * k[6] + q[7] * k[7];
        d += __shfl_xor_sync(0xffffffffu, d, 1);
        d += __shfl_xor_sync(0xffffffffu, d, 2);
        d += __shfl_xor_sync(0xffffffffu, d, 4);
        // scores are tiny (|s| << 1): exp without max-subtraction is exact here
        float e = __expf(d * fh);
        if (sub == 0) g_esc[((size_t)r * EE + p) * HH + h] = e;
        ssum += e;
    }
    float inv = 1.f / (ssum + 1e-10f);

    // pass B: attn-weighted V aggregation in registers (no atomics)
    float acc[8] = {0.f, 0.f, 0.f, 0.f, 0.f, 0.f, 0.f, 0.f};
    for (int p = beg; p < end; p++) {
        int tgt = g_csr[(size_t)r * EE + p];
        float ev = 0.f;
        if (sub == 0) ev = g_esc[((size_t)r * EE + p) * HH + h];
        ev = __shfl_sync(0xffffffffu, ev, lane & 24);  // broadcast from writer lane
        float a = ev * inv;
        const float* vp = g_V + ((size_t)r * NN + tgt) * HD + h * 64 + sub * 8;
        float4 v0 = *reinterpret_cast<const float4*>(vp);
        float4 v1 = *reinterpret_cast<const float4*>(vp + 4);
        acc[0] += a * v0.x; acc[1] += a * v0.y; acc[2] += a * v0.z; acc[3] += a * v0.w;
        acc[4] += a * v1.x; acc[5] += a * v1.y; acc[6] += a * v1.z; acc[7] += a * v1.w;
    }
    float* op = g_comb + (size_t)node * RHD + r * HD + h * 64 + sub * 8;
    *reinterpret_cast<float4*>(op)     = make_float4(acc[0], acc[1], acc[2], acc[3]);
    *reinterpret_cast<float4*>(op + 4) = make_float4(acc[4], acc[5], acc[6], acc[7]);
}

// ---------------- 6: output projection  comb[N,1024] @ Wo[1024,64] + bo --------
__global__ void __launch_bounds__(256) out_gemm(const float* __restrict__ Wo,
                                                const float* __restrict__ bo,
                                                float* __restrict__ out) {
    __shared__ float As[32][64];  // transposed
    __shared__ float Bs[32][64];
    int row0 = blockIdx.x * 64;
    int tid = threadIdx.x;
    int tx = tid & 15, ty = tid >> 4;
    float acc[4][4] = {};

    for (int k0 = 0; k0 < RHD; k0 += 32) {
#pragma unroll
        for (int i = tid * 4; i < 64 * 32; i += 1024) {
            int rr = i >> 5, kk = i & 31;
            int row = row0 + rr;
            float4 v = make_float4(0.f, 0.f, 0.f, 0.f);
            if (row < NN)
                v = *reinterpret_cast<const float4*>(g_comb + (size_t)row * RHD + k0 + kk);
            As[kk + 0][rr] = v.x; As[kk + 1][rr] = v.y;
            As[kk + 2][rr] = v.z; As[kk + 3][rr] = v.w;
        }
#pragma unroll
        for (int i = tid * 4; i < 32 * 64; i += 1024) {
            int kk = i >> 6, cc = i & 63;
            *reinterpret_cast<float4*>(&Bs[kk][cc]) =
                *reinterpret_cast<const float4*>(Wo + (size_t)(k0 + kk) * 64 + cc);
        }
        __syncthreads();
#pragma unroll
        for (int kk = 0; kk < 32; kk++) {
            float a[4], b[4];
            *reinterpret_cast<float4*>(a) = *reinterpret_cast<const float4*>(&As[kk][ty * 4]);
            *reinterpret_cast<float4*>(b) = *reinterpret_cast<const float4*>(&Bs[kk][tx * 4]);
#pragma unroll
            for (int i = 0; i < 4; i++)
#pragma unroll
                for (int j = 0; j < 4; j++) acc[i][j] += a[i] * b[j];
        }
        __syncthreads();
    }
#pragma unroll
    for (int i = 0; i < 4; i++) {
        int row = row0 + ty * 4 + i;
        if (row >= NN) continue;
        float4 v = make_float4(acc[i][0] + bo[tx * 4 + 0], acc[i][1] + bo[tx * 4 + 1],
                               acc[i][2] + bo[tx * 4 + 2], acc[i][3] + bo[tx * 4 + 3]);
        *reinterpret_cast<float4*>(out + (size_t)row * 64 + tx * 4) = v;
    }
}

// ---------------- launch ----------------
extern "C" void kernel_launch(void* const* d_in, const int* in_sizes, int n_in,
                              void* d_out, int out_size) {
    const float* X    = (const float*)d_in[0];
    const float* infl = (const float*)d_in[1];
    const int*   esrc = (const int*)d_in[2];
    const int*   etgt = (const int*)d_in[3];
    const float* Wq   = (const float*)d_in[4];
    const float* bq   = (const float*)d_in[5];
    const float* Wk   = (const float*)d_in[6];
    const float* bk   = (const float*)d_in[7];
    const float* Wv   = (const float*)d_in[8];
    const float* bv   = (const float*)d_in[9];
    const float* sw   = (const float*)d_in[10];
    const float* Wo   = (const float*)d_in[11];
    const float* bo   = (const float*)d_in[12];
    float* out = (float*)d_out;

    zero_cnt_kernel<<<(RR * NN + 255) / 256, 256>>>();
    qkv_gemm<<<dim3((NN + 127) / 128, 2, 12), 256>>>(X, Wq, bq, Wk, bk, Wv, bv);
    hist_kernel<<<dim3((EE + 255) / 256, RR), 256>>>(esrc);
    scan_kernel<<<RR, 1024>>>();
    scatter_kernel<<<dim3((EE + 255) / 256, RR), 256>>>(esrc, etgt);
    attn_kernel<<<dim3((NN + 7) / 8, RR), 256>>>(infl, sw);
    out_gemm<<<(NN + 63) / 64, 256>>>(Wo, bo, out);
}

// round 2
// speedup vs baseline: 1.4277x; 1.4277x over previous
#include <cuda_runtime.h>
#include <cuda_bf16.h>
#include <cstdint>

#define NN 50000
#define DD 64
#define HH 4
#define RR 4
#define EE 800000
#define HD 256     // H*D
#define RHD 1024   // R*H*D
#define NCHUNK 25  // ceil(NN / 2048)

// ---------------- scratch (static device globals; no allocation) ----------------
__device__ __nv_bfloat16 g_Q[(size_t)RR * NN * HD];   // 102.4 MB
__device__ __nv_bfloat16 g_K[(size_t)RR * NN * HD];   // 102.4 MB
__device__ float         g_V[(size_t)RR * NN * HD];   // 204.8 MB
__device__ float         g_comb[(size_t)NN * RHD];    // 204.8 MB
__device__ int           g_cnt[RR * NN];
__device__ int           g_off[RR * (NN + 1)];
__device__ int           g_cur[RR * NN];
__device__ int           g_csr[(size_t)RR * EE];      // 12.8 MB
__device__ int           g_bsum[RR * 32];

// ---------------- helpers ----------------
__device__ __forceinline__ void ld_bf16x8(const __nv_bfloat16* p, float* f) {
    uint4 u = *reinterpret_cast<const uint4*>(p);
    unsigned w[4] = {u.x, u.y, u.z, u.w};
#pragma unroll
    for (int i = 0; i < 4; i++) {
        float2 t = __bfloat1622float2(*reinterpret_cast<__nv_bfloat162*>(&w[i]));
        f[2 * i] = t.x;
        f[2 * i + 1] = t.y;
    }
}

__device__ __forceinline__ unsigned f2tf32(float x) {
    unsigned u;
    asm("cvt.rna.tf32.f32 %0, %1;" : "=r"(u) : "f"(x));
    return u;
}

__device__ __forceinline__ void mma_tf32(float* c, const unsigned* a, const unsigned* b) {
    asm volatile(
        "mma.sync.aligned.m16n8k8.row.col.f32.tf32.tf32.f32 "
        "{%0,%1,%2,%3}, {%4,%5,%6,%7}, {%8,%9}, {%0,%1,%2,%3};"
        : "+f"(c[0]), "+f"(c[1]), "+f"(c[2]), "+f"(c[3])
        : "r"(a[0]), "r"(a[1]), "r"(a[2]), "r"(a[3]), "r"(b[0]), "r"(b[1]));
}

// ---------------- 0: zero histogram ----------------
__global__ void zero_cnt_kernel() {
    int i = blockIdx.x * blockDim.x + threadIdx.x;
    if (i < RR * NN) g_cnt[i] = 0;
}

// ---------------- 1: QKV projections via tf32 tensor-core mma ----------------
// C[N,256] = X[N,64] @ W[64,256] + b, 12 matrices (R * {Q,K,V}).
// Block tile: M=128, N=128 (blockIdx.y = col half). 8 warps as 4(M) x 2(N);
// warp tile M=32, N=64, K=64 -> 2 m-tiles x 8 n-tiles x 8 k-tiles of m16n8k8.
#define AS_STRIDE 68
#define BS_STRIDE 136
#define QKV_SMEM ((128 * AS_STRIDE + 64 * BS_STRIDE) * 4)

__global__ void __launch_bounds__(256, 2) qkv_mma(
    const float* __restrict__ X,
    const float* __restrict__ Wq, const float* __restrict__ bq,
    const float* __restrict__ Wk, const float* __restrict__ bk,
    const float* __restrict__ Wv, const float* __restrict__ bv) {
    extern __shared__ unsigned smem[];
    unsigned* As = smem;                      // [128][68]
    unsigned* Bs = smem + 128 * AS_STRIDE;    // [64][136]

    int m = blockIdx.z;
    int r = m / 3, t = m % 3;
    const float* W    = (t == 0 ? Wq : t == 1 ? Wk : Wv) + (size_t)r * DD * HD;
    const float* bias = (t == 0 ? bq : t == 1 ? bk : bv) + (size_t)r * HD;
    int row0 = blockIdx.x * 128;
    int col0 = blockIdx.y * 128;
    int tid = threadIdx.x;

    // stage A (X tile, tf32-rounded): 128 rows x 64 k
#pragma unroll
    for (int i = tid; i < 128 * 16; i += 256) {
        int rr = i >> 4, kq = (i & 15) << 2;
        int row = row0 + rr;
        float4 v = make_float4(0.f, 0.f, 0.f, 0.f);
        if (row < NN)
            v = *reinterpret_cast<const float4*>(X + (size_t)row * DD + kq);
        unsigned* dst = As + rr * AS_STRIDE + kq;
        dst[0] = f2tf32(v.x); dst[1] = f2tf32(v.y);
        dst[2] = f2tf32(v.z); dst[3] = f2tf32(v.w);
    }
    // stage B (W tile): 64 k x 128 cols
#pragma unroll
    for (int i = tid; i < 64 * 32; i += 256) {
        int kk = i >> 5, cq = (i & 31) << 2;
        float4 v = *reinterpret_cast<const float4*>(W + (size_t)kk * HD + col0 + cq);
        unsigned* dst = Bs + kk * BS_STRIDE + cq;
        dst[0] = f2tf32(v.x); dst[1] = f2tf32(v.y);
        dst[2] = f2tf32(v.z); dst[3] = f2tf32(v.w);
    }
    __syncthreads();

    int wid = tid >> 5, lane = tid & 31;
    int wm = (wid >> 1) * 32;   // 0,32,64,96
    int wn = (wid & 1) * 64;    // 0,64
    int g = lane >> 2, tg = lane & 3;

    float acc[2][8][4] = {};
#pragma unroll
    for (int kt = 0; kt < 8; kt++) {
        int k0 = kt * 8;
        unsigned a[2][4], b[8][2];
#pragma unroll
        for (int mt = 0; mt < 2; mt++) {
            int mr = wm + mt * 16;
            a[mt][0] = As[(mr + g) * AS_STRIDE + k0 + tg];
            a[mt][1] = As[(mr + g + 8) * AS_STRIDE + k0 + tg];
            a[mt][2] = As[(mr + g) * AS_STRIDE + k0 + tg + 4];
            a[mt][3] = As[(mr + g + 8) * AS_STRIDE + k0 + tg + 4];
        }
#pragma unroll
        for (int nt = 0; nt < 8; nt++) {
            int nc = wn + nt * 8;
            b[nt][0] = Bs[(k0 + tg) * BS_STRIDE + nc + g];
            b[nt][1] = Bs[(k0 + tg + 4) * BS_STRIDE + nc + g];
        }
#pragma unroll
        for (int mt = 0; mt < 2; mt++)
#pragma unroll
            for (int nt = 0; nt < 8; nt++)
                mma_tf32(acc[mt][nt], a[mt], b[nt]);
    }

    // epilogue: add bias, store. c0:(rA,c) c1:(rA,c+1) c2:(rB,c) c3:(rB,c+1)
#pragma unroll
    for (int mt = 0; mt < 2; mt++) {
        int rA = row0 + wm + mt * 16 + g;
        int rB = rA + 8;
#pragma unroll
        for (int nt = 0; nt < 8; nt++) {
            int c = col0 + wn + nt * 8 + 2 * tg;
            float b0 = bias[c], b1 = bias[c + 1];
            float v00 = acc[mt][nt][0] + b0, v01 = acc[mt][nt][1] + b1;
            float v10 = acc[mt][nt][2] + b0, v11 = acc[mt][nt][3] + b1;
            if (t == 2) {
                if (rA < NN)
                    *reinterpret_cast<float2*>(g_V + ((size_t)r * NN + rA) * HD + c) =
                        make_float2(v00, v01);
                if (rB < NN)
                    *reinterpret_cast<float2*>(g_V + ((size_t)r * NN + rB) * HD + c) =
                        make_float2(v10, v11);
            } else {
                __nv_bfloat16* base = (t == 0 ? g_Q : g_K);
                if (rA < NN) {
                    __nv_bfloat162 p = __floats2bfloat162_rn(v00, v01);
                    *reinterpret_cast<__nv_bfloat162*>(base + ((size_t)r * NN + rA) * HD + c) = p;
                }
                if (rB < NN) {
                    __nv_bfloat162 p = __floats2bfloat162_rn(v10, v11);
                    *reinterpret_cast<__nv_bfloat162*>(base + ((size_t)r * NN + rB) * HD + c) = p;
                }
            }
        }
    }
}

// ---------------- 2: histogram of edges per src ----------------
__global__ void hist_kernel(const int* __restrict__ esrc) {
    int r = blockIdx.y;
    int i = blockIdx.x * blockDim.x + threadIdx.x;
    if (i < EE) atomicAdd(&g_cnt[r * NN + esrc[(size_t)r * EE + i]], 1);
}

// ---------------- 3: parallel 3-phase exclusive scan ----------------
__global__ void __launch_bounds__(1024) scan_part() {
    int r = blockIdx.y, ch = blockIdx.x;
    int t = threadIdx.x, lane = t & 31, wid = t >> 5;
    int i0 = ch * 2048 + 2 * t, i1 = i0 + 1;
    int v0 = (i0 < NN) ? g_cnt[r * NN + i0] : 0;
    int v1 = (i1 < NN) ? g_cnt[r * NN + i1] : 0;
    int s = v0 + v1;
    int x = s;
#pragma unroll
    for (int o = 1; o < 32; o <<= 1) {
        int y = __shfl_up_sync(0xffffffffu, x, o);
        if (lane >= o) x += y;
    }
    __shared__ int wsum[32];
    if (lane == 31) wsum[wid] = x;
    __syncthreads();
    if (wid == 0) {
        int w = wsum[lane];
#pragma unroll
        for (int o = 1; o < 32; o <<= 1) {
            int y = __shfl_up_sync(0xffffffffu, w, o);
            if (lane >= o) w += y;
        }
        wsum[lane] = w;
    }
    __syncthreads();
    int excl = x - s + (wid > 0 ? wsum[wid - 1] : 0);
    if (i0 < NN) g_off[r * (NN + 1) + i0] = excl;
    if (i1 < NN) g_off[r * (NN + 1) + i1] = excl + v0;
    if (t == 1023) g_bsum[r * 32 + ch] = excl + s;
}

__global__ void scan_bsum() {
    int wid = threadIdx.x >> 5, lane = threadIdx.x & 31;
    if (wid < RR) {
        int v = (lane < NCHUNK) ? g_bsum[wid * 32 + lane] : 0;
        int x = v;
#pragma unroll
        for (int o = 1; o < 32; o <<= 1) {
            int y = __shfl_up_sync(0xffffffffu, x, o);
            if (lane >= o) x += y;
        }
        if (lane < NCHUNK) g_bsum[wid * 32 + lane] = x - v;
        if (lane == NCHUNK - 1) g_off[wid * (NN + 1) + NN] = x;
    }
}

__global__ void __launch_bounds__(1024) scan_add() {
    int r = blockIdx.y, ch = blockIdx.x;
    int off = g_bsum[r * 32 + ch];
    int i0 = ch * 2048 + 2 * threadIdx.x;
#pragma unroll
    for (int k = 0; k < 2; k++) {
        int i = i0 + k;
        if (i < NN) {
            int v = g_off[r * (NN + 1) + i] + off;
            g_off[r * (NN + 1) + i] = v;
            g_cur[r * NN + i] = v;
        }
    }
}

// ---------------- 4: scatter edges into CSR ----------------
__global__ void scatter_kernel(const int* __restrict__ esrc, const int* __restrict__ etgt) {
    int r = blockIdx.y;
    int i = blockIdx.x * blockDim.x + threadIdx.x;
    if (i < EE) {
        int s = esrc[(size_t)r * EE + i];
        int pos = atomicAdd(&g_cur[r * NN + s], 1);
        g_csr[(size_t)r * EE + pos] = etgt[(size_t)r * EE + i];
    }
}

// ---------------- 5: fused SINGLE-PASS edge-softmax + aggregation --------------
// One warp per (r,node). Lane: head h = lane>>3, sub = lane&7.
// No max-subtraction (scores tiny) => numerator and denominator in one loop.
__global__ void __launch_bounds__(256) attn_kernel(const float* __restrict__ infl,
                                                   const float* __restrict__ signw) {
    int r = blockIdx.y;
    int node = blockIdx.x * 8 + (threadIdx.x >> 5);
    if (node >= NN) return;
    int lane = threadIdx.x & 31;
    int h = lane >> 3, sub = lane & 7;
    int lo = h * 64 + sub * 8;

    float q[8];
    ld_bf16x8(g_Q + ((size_t)r * NN + node) * HD + lo, q);
    float fh = infl[node] * signw[h * RR + r] * 0.125f;  // 1/sqrt(64)

    int beg = g_off[r * (NN + 1) + node];
    int end = g_off[r * (NN + 1) + node + 1];
    const int* csr = g_csr + (size_t)r * EE;

    float ssum = 0.f;
    float acc[8] = {0.f, 0.f, 0.f, 0.f, 0.f, 0.f, 0.f, 0.f};
    int tgt = (beg < end) ? csr[beg] : 0;
    for (int p = beg; p < end; p++) {
        int nxt = (p + 1 < end) ? csr[p + 1] : 0;
        size_t rowo = ((size_t)r * NN + tgt) * HD + lo;
        float k[8];
        ld_bf16x8(g_K + rowo, k);
        float4 v0 = *reinterpret_cast<const float4*>(g_V + rowo);
        float4 v1 = *reinterpret_cast<const float4*>(g_V + rowo + 4);
        float d = q[0] * k[0] + q[1] * k[1] + q[2] * k[2] + q[3] * k[3] +
                  q[4] * k[4] + q[5] * k[5] + q[6] * k[6] + q[7] * k[7];
        d += __shfl_xor_sync(0xffffffffu, d, 1);
        d += __shfl_xor_sync(0xffffffffu, d, 2);
        d += __shfl_xor_sync(0xffffffffu, d, 4);
        float e = __expf(d * fh);
        ssum += e;
        acc[0] += e * v0.x; acc[1] += e * v0.y; acc[2] += e * v0.z; acc[3] += e * v0.w;
        acc[4] += e * v1.x; acc[5] += e * v1.y; acc[6] += e * v1.z; acc[7] += e * v1.w;
        tgt = nxt;
    }
    float inv = 1.f / (ssum + 1e-10f);
    float* op = g_comb + (size_t)node * RHD + r * HD + lo;
    *reinterpret_cast<float4*>(op) =
        make_float4(acc[0] * inv, acc[1] * inv, acc[2] * inv, acc[3] * inv);
    *reinterpret_cast<float4*>(op + 4) =
        make_float4(acc[4] * inv, acc[5] * inv, acc[6] * inv, acc[7] * inv);
}

// ---------------- 6: output projection  comb[N,1024] @ Wo[1024,64] + bo --------
__global__ void __launch_bounds__(256) out_gemm(const float* __restrict__ Wo,
                                                const float* __restrict__ bo,
                                                float* __restrict__ out) {
    __shared__ float As[32][64];  // transposed
    __shared__ float Bs[32][64];
    int row0 = blockIdx.x * 64;
    int tid = threadIdx.x;
    int tx = tid & 15, ty = tid >> 4;
    float acc[4][4] = {};

    for (int k0 = 0; k0 < RHD; k0 += 32) {
#pragma unroll
        for (int i = tid * 4; i < 64 * 32; i += 1024) {
            int rr = i >> 5, kk = i & 31;
            int row = row0 + rr;
            float4 v = make_float4(0.f, 0.f, 0.f, 0.f);
            if (row < NN)
                v = *reinterpret_cast<const float4*>(g_comb + (size_t)row * RHD + k0 + kk);
            As[kk + 0][rr] = v.x; As[kk + 1][rr] = v.y;
            As[kk + 2][rr] = v.z; As[kk + 3][rr] = v.w;
        }
#pragma unroll
        for (int i = tid * 4; i < 32 * 64; i += 1024) {
            int kk = i >> 6, cc = i & 63;
            *reinterpret_cast<float4*>(&Bs[kk][cc]) =
                *reinterpret_cast<const float4*>(Wo + (size_t)(k0 + kk) * 64 + cc);
        }
        __syncthreads();
#pragma unroll
        for (int kk = 0; kk < 32; kk++) {
            float a[4], b[4];
            *reinterpret_cast<float4*>(a) = *reinterpret_cast<const float4*>(&As[kk][ty * 4]);
            *reinterpret_cast<float4*>(b) = *reinterpret_cast<const float4*>(&Bs[kk][tx * 4]);
#pragma unroll
            for (int i = 0; i < 4; i++)
#pragma unroll
                for (int j = 0; j < 4; j++) acc[i][j] += a[i] * b[j];
        }
        __syncthreads();
    }
#pragma unroll
    for (int i = 0; i < 4; i++) {
        int row = row0 + ty * 4 + i;
        if (row >= NN) continue;
        float4 v = make_float4(acc[i][0] + bo[tx * 4 + 0], acc[i][1] + bo[tx * 4 + 1],
                               acc[i][2] + bo[tx * 4 + 2], acc[i][3] + bo[tx * 4 + 3]);
        *reinterpret_cast<float4*>(out + (size_t)row * 64 + tx * 4) = v;
    }
}

// ---------------- launch ----------------
extern "C" void kernel_launch(void* const* d_in, const int* in_sizes, int n_in,
                              void* d_out, int out_size) {
    const float* X    = (const float*)d_in[0];
    const float* infl = (const float*)d_in[1];
    const int*   esrc = (const int*)d_in[2];
    const int*   etgt = (const int*)d_in[3];
    const float* Wq   = (const float*)d_in[4];
    const float* bq   = (const float*)d_in[5];
    const float* Wk   = (const float*)d_in[6];
    const float* bk   = (const float*)d_in[7];
    const float* Wv   = (const float*)d_in[8];
    const float* bv   = (const float*)d_in[9];
    const float* sw   = (const float*)d_in[10];
    const float* Wo   = (const float*)d_in[11];
    const float* bo   = (const float*)d_in[12];
    float* out = (float*)d_out;

    cudaFuncSetAttribute(qkv_mma, cudaFuncAttributeMaxDynamicSharedMemorySize, QKV_SMEM);

    zero_cnt_kernel<<<(RR * NN + 255) / 256, 256>>>();
    qkv_mma<<<dim3((NN + 127) / 128, 2, 12), 256, QKV_SMEM>>>(X, Wq, bq, Wk, bk, Wv, bv);
    hist_kernel<<<dim3((EE + 255) / 256, RR), 256>>>(esrc);
    scan_part<<<dim3(NCHUNK, RR), 1024>>>();
    scan_bsum<<<1, 128>>>();
    scan_add<<<dim3(NCHUNK, RR), 1024>>>();
    scatter_kernel<<<dim3((EE + 255) / 256, RR), 256>>>(esrc, etgt);
    attn_kernel<<<dim3((NN + 7) / 8, RR), 256>>>(infl, sw);
    out_gemm<<<(NN + 63) / 64, 256>>>(Wo, bo, out);
}

// round 3
// speedup vs baseline: 1.7898x; 1.2536x over previous
#include <cuda_runtime.h>
#include <cuda_bf16.h>
#include <cstdint>

#define NN 50000
#define DD 64
#define HH 4
#define RR 4
#define EE 800000
#define HD 256     // H*D
#define RHD 1024   // R*H*D
#define NCHUNK 25  // ceil(NN / 2048)

// ---------------- scratch (static device globals; no allocation) ----------------
__device__ __nv_bfloat16 g_Q[(size_t)RR * NN * HD];   // 102.4 MB
__device__ __nv_bfloat16 g_K[(size_t)RR * NN * HD];   // 102.4 MB
__device__ float         g_V[(size_t)RR * NN * HD];   // 204.8 MB
__device__ float         g_comb[(size_t)NN * RHD];    // 204.8 MB
__device__ int           g_cnt[RR * NN];
__device__ int           g_off[RR * (NN + 1)];
__device__ int           g_cur[RR * NN];
__device__ int           g_csr[(size_t)RR * EE];      // 12.8 MB
__device__ int           g_bsum[RR * 32];

// ---------------- helpers ----------------
__device__ __forceinline__ void ld_bf16x8(const __nv_bfloat16* p, float* f) {
    uint4 u = *reinterpret_cast<const uint4*>(p);
    unsigned w[4] = {u.x, u.y, u.z, u.w};
#pragma unroll
    for (int i = 0; i < 4; i++) {
        float2 t = __bfloat1622float2(*reinterpret_cast<__nv_bfloat162*>(&w[i]));
        f[2 * i] = t.x;
        f[2 * i + 1] = t.y;
    }
}

__device__ __forceinline__ unsigned f2tf32(float x) {
    unsigned u;
    asm("cvt.rna.tf32.f32 %0, %1;" : "=r"(u) : "f"(x));
    return u;
}

__device__ __forceinline__ void mma_tf32(float* c, const unsigned* a, const unsigned* b) {
    asm volatile(
        "mma.sync.aligned.m16n8k8.row.col.f32.tf32.tf32.f32 "
        "{%0,%1,%2,%3}, {%4,%5,%6,%7}, {%8,%9}, {%0,%1,%2,%3};"
        : "+f"(c[0]), "+f"(c[1]), "+f"(c[2]), "+f"(c[3])
        : "r"(a[0]), "r"(a[1]), "r"(a[2]), "r"(a[3]), "r"(b[0]), "r"(b[1]));
}

// ---------------- 0: zero histogram ----------------
__global__ void zero_cnt_kernel() {
    int i = blockIdx.x * blockDim.x + threadIdx.x;
    if (i < RR * NN) g_cnt[i] = 0;
}

// ---------------- 1: QKV projections via tf32 tensor-core mma ----------------
#define AS_STRIDE 68
#define BS_STRIDE 136
#define QKV_SMEM ((128 * AS_STRIDE + 64 * BS_STRIDE) * 4)

__global__ void __launch_bounds__(256, 2) qkv_mma(
    const float* __restrict__ X,
    const float* __restrict__ Wq, const float* __restrict__ bq,
    const float* __restrict__ Wk, const float* __restrict__ bk,
    const float* __restrict__ Wv, const float* __restrict__ bv) {
    extern __shared__ unsigned smem[];
    unsigned* As = smem;                      // [128][68]
    unsigned* Bs = smem + 128 * AS_STRIDE;    // [64][136]

    int m = blockIdx.z;
    int r = m / 3, t = m % 3;
    const float* W    = (t == 0 ? Wq : t == 1 ? Wk : Wv) + (size_t)r * DD * HD;
    const float* bias = (t == 0 ? bq : t == 1 ? bk : bv) + (size_t)r * HD;
    int row0 = blockIdx.x * 128;
    int col0 = blockIdx.y * 128;
    int tid = threadIdx.x;

#pragma unroll
    for (int i = tid; i < 128 * 16; i += 256) {
        int rr = i >> 4, kq = (i & 15) << 2;
        int row = row0 + rr;
        float4 v = make_float4(0.f, 0.f, 0.f, 0.f);
        if (row < NN)
            v = *reinterpret_cast<const float4*>(X + (size_t)row * DD + kq);
        unsigned* dst = As + rr * AS_STRIDE + kq;
        dst[0] = f2tf32(v.x); dst[1] = f2tf32(v.y);
        dst[2] = f2tf32(v.z); dst[3] = f2tf32(v.w);
    }
#pragma unroll
    for (int i = tid; i < 64 * 32; i += 256) {
        int kk = i >> 5, cq = (i & 31) << 2;
        float4 v = *reinterpret_cast<const float4*>(W + (size_t)kk * HD + col0 + cq);
        unsigned* dst = Bs + kk * BS_STRIDE + cq;
        dst[0] = f2tf32(v.x); dst[1] = f2tf32(v.y);
        dst[2] = f2tf32(v.z); dst[3] = f2tf32(v.w);
    }
    __syncthreads();

    int wid = tid >> 5, lane = tid & 31;
    int wm = (wid >> 1) * 32;
    int wn = (wid & 1) * 64;
    int g = lane >> 2, tg = lane & 3;

    float acc[2][8][4] = {};
#pragma unroll
    for (int kt = 0; kt < 8; kt++) {
        int k0 = kt * 8;
        unsigned a[2][4], b[8][2];
#pragma unroll
        for (int mt = 0; mt < 2; mt++) {
            int mr = wm + mt * 16;
            a[mt][0] = As[(mr + g) * AS_STRIDE + k0 + tg];
            a[mt][1] = As[(mr + g + 8) * AS_STRIDE + k0 + tg];
            a[mt][2] = As[(mr + g) * AS_STRIDE + k0 + tg + 4];
            a[mt][3] = As[(mr + g + 8) * AS_STRIDE + k0 + tg + 4];
        }
#pragma unroll
        for (int nt = 0; nt < 8; nt++) {
            int nc = wn + nt * 8;
            b[nt][0] = Bs[(k0 + tg) * BS_STRIDE + nc + g];
            b[nt][1] = Bs[(k0 + tg + 4) * BS_STRIDE + nc + g];
        }
#pragma unroll
        for (int mt = 0; mt < 2; mt++)
#pragma unroll
            for (int nt = 0; nt < 8; nt++)
                mma_tf32(acc[mt][nt], a[mt], b[nt]);
    }

#pragma unroll
    for (int mt = 0; mt < 2; mt++) {
        int rA = row0 + wm + mt * 16 + g;
        int rB = rA + 8;
#pragma unroll
        for (int nt = 0; nt < 8; nt++) {
            int c = col0 + wn + nt * 8 + 2 * tg;
            float b0 = bias[c], b1 = bias[c + 1];
            float v00 = acc[mt][nt][0] + b0, v01 = acc[mt][nt][1] + b1;
            float v10 = acc[mt][nt][2] + b0, v11 = acc[mt][nt][3] + b1;
            if (t == 2) {
                if (rA < NN)
                    *reinterpret_cast<float2*>(g_V + ((size_t)r * NN + rA) * HD + c) =
                        make_float2(v00, v01);
                if (rB < NN)
                    *reinterpret_cast<float2*>(g_V + ((size_t)r * NN + rB) * HD + c) =
                        make_float2(v10, v11);
            } else {
                __nv_bfloat16* base = (t == 0 ? g_Q : g_K);
                if (rA < NN) {
                    __nv_bfloat162 p = __floats2bfloat162_rn(v00, v01);
                    *reinterpret_cast<__nv_bfloat162*>(base + ((size_t)r * NN + rA) * HD + c) = p;
                }
                if (rB < NN) {
                    __nv_bfloat162 p = __floats2bfloat162_rn(v10, v11);
                    *reinterpret_cast<__nv_bfloat162*>(base + ((size_t)r * NN + rB) * HD + c) = p;
                }
            }
        }
    }
}

// ---------------- 2: histogram of edges per src ----------------
__global__ void hist_kernel(const int* __restrict__ esrc) {
    int r = blockIdx.y;
    int i = blockIdx.x * blockDim.x + threadIdx.x;
    if (i < EE) atomicAdd(&g_cnt[r * NN + esrc[(size_t)r * EE + i]], 1);
}

// ---------------- 3: parallel 3-phase exclusive scan ----------------
__global__ void __launch_bounds__(1024) scan_part() {
    int r = blockIdx.y, ch = blockIdx.x;
    int t = threadIdx.x, lane = t & 31, wid = t >> 5;
    int i0 = ch * 2048 + 2 * t, i1 = i0 + 1;
    int v0 = (i0 < NN) ? g_cnt[r * NN + i0] : 0;
    int v1 = (i1 < NN) ? g_cnt[r * NN + i1] : 0;
    int s = v0 + v1;
    int x = s;
#pragma unroll
    for (int o = 1; o < 32; o <<= 1) {
        int y = __shfl_up_sync(0xffffffffu, x, o);
        if (lane >= o) x += y;
    }
    __shared__ int wsum[32];
    if (lane == 31) wsum[wid] = x;
    __syncthreads();
    if (wid == 0) {
        int w = wsum[lane];
#pragma unroll
        for (int o = 1; o < 32; o <<= 1) {
            int y = __shfl_up_sync(0xffffffffu, w, o);
            if (lane >= o) w += y;
        }
        wsum[lane] = w;
    }
    __syncthreads();
    int excl = x - s + (wid > 0 ? wsum[wid - 1] : 0);
    if (i0 < NN) g_off[r * (NN + 1) + i0] = excl;
    if (i1 < NN) g_off[r * (NN + 1) + i1] = excl + v0;
    if (t == 1023) g_bsum[r * 32 + ch] = excl + s;
}

__global__ void scan_bsum() {
    int wid = threadIdx.x >> 5, lane = threadIdx.x & 31;
    if (wid < RR) {
        int v = (lane < NCHUNK) ? g_bsum[wid * 32 + lane] : 0;
        int x = v;
#pragma unroll
        for (int o = 1; o < 32; o <<= 1) {
            int y = __shfl_up_sync(0xffffffffu, x, o);
            if (lane >= o) x += y;
        }
        if (lane < NCHUNK) g_bsum[wid * 32 + lane] = x - v;
        if (lane == NCHUNK - 1) g_off[wid * (NN + 1) + NN] = x;
    }
}

__global__ void __launch_bounds__(1024) scan_add() {
    int r = blockIdx.y, ch = blockIdx.x;
    int off = g_bsum[r * 32 + ch];
    int i0 = ch * 2048 + 2 * threadIdx.x;
#pragma unroll
    for (int k = 0; k < 2; k++) {
        int i = i0 + k;
        if (i < NN) {
            int v = g_off[r * (NN + 1) + i] + off;
            g_off[r * (NN + 1) + i] = v;
            g_cur[r * NN + i] = v;
        }
    }
}

// ---------------- 4: scatter edges into CSR ----------------
__global__ void scatter_kernel(const int* __restrict__ esrc, const int* __restrict__ etgt) {
    int r = blockIdx.y;
    int i = blockIdx.x * blockDim.x + threadIdx.x;
    if (i < EE) {
        int s = esrc[(size_t)r * EE + i];
        int pos = atomicAdd(&g_cur[r * NN + s], 1);
        g_csr[(size_t)r * EE + pos] = etgt[(size_t)r * EE + i];
    }
}

// ---------------- 5: fused single-pass softmax+agg, 2-edge unrolled -----------
// One warp per (r,node). Lane: head h = lane>>3, sub = lane&7.
__global__ void __launch_bounds__(256) attn_kernel(const float* __restrict__ infl,
                                                   const float* __restrict__ signw) {
    int r = blockIdx.y;
    int node = blockIdx.x * 8 + (threadIdx.x >> 5);
    if (node >= NN) return;
    int lane = threadIdx.x & 31;
    int h = lane >> 3, sub = lane & 7;
    int lo = h * 64 + sub * 8;

    float q[8];
    ld_bf16x8(g_Q + ((size_t)r * NN + node) * HD + lo, q);
    float fh = infl[node] * signw[h * RR + r] * 0.125f;  // 1/sqrt(64)

    int beg = g_off[r * (NN + 1) + node];
    int end = g_off[r * (NN + 1) + node + 1];
    const int* csr = g_csr + (size_t)r * EE;

    float ssum = 0.f;
    float acc[8] = {0.f, 0.f, 0.f, 0.f, 0.f, 0.f, 0.f, 0.f};

    int p = beg;
    for (; p + 2 <= end; p += 2) {
        int t0 = csr[p], t1 = csr[p + 1];
        size_t o0 = ((size_t)r * NN + t0) * HD + lo;
        size_t o1 = ((size_t)r * NN + t1) * HD + lo;
        // issue all 6 loads up front (2x K, 4x V quads) for MLP
        float k0[8], k1[8];
        ld_bf16x8(g_K + o0, k0);
        ld_bf16x8(g_K + o1, k1);
        float4 v00 = *reinterpret_cast<const float4*>(g_V + o0);
        float4 v01 = *reinterpret_cast<const float4*>(g_V + o0 + 4);
        float4 v10 = *reinterpret_cast<const float4*>(g_V + o1);
        float4 v11 = *reinterpret_cast<const float4*>(g_V + o1 + 4);

        float d0 = q[0] * k0[0] + q[1] * k0[1] + q[2] * k0[2] + q[3] * k0[3] +
                   q[4] * k0[4] + q[5] * k0[5] + q[6] * k0[6] + q[7] * k0[7];
        float d1 = q[0] * k1[0] + q[1] * k1[1] + q[2] * k1[2] + q[3] * k1[3] +
                   q[4] * k1[4] + q[5] * k1[5] + q[6] * k1[6] + q[7] * k1[7];
        d0 += __shfl_xor_sync(0xffffffffu, d0, 1);
        d1 += __shfl_xor_sync(0xffffffffu, d1, 1);
        d0 += __shfl_xor_sync(0xffffffffu, d0, 2);
        d1 += __shfl_xor_sync(0xffffffffu, d1, 2);
        d0 += __shfl_xor_sync(0xffffffffu, d0, 4);
        d1 += __shfl_xor_sync(0xffffffffu, d1, 4);
        float e0 = __expf(d0 * fh);
        float e1 = __expf(d1 * fh);
        ssum += e0 + e1;
        acc[0] += e0 * v00.x + e1 * v10.x;
        acc[1] += e0 * v00.y + e1 * v10.y;
        acc[2] += e0 * v00.z + e1 * v10.z;
        acc[3] += e0 * v00.w + e1 * v10.w;
        acc[4] += e0 * v01.x + e1 * v11.x;
        acc[5] += e0 * v01.y + e1 * v11.y;
        acc[6] += e0 * v01.z + e1 * v11.z;
        acc[7] += e0 * v01.w + e1 * v11.w;
    }
    if (p < end) {
        int t0 = csr[p];
        size_t o0 = ((size_t)r * NN + t0) * HD + lo;
        float k0[8];
        ld_bf16x8(g_K + o0, k0);
        float4 v00 = *reinterpret_cast<const float4*>(g_V + o0);
        float4 v01 = *reinterpret_cast<const float4*>(g_V + o0 + 4);
        float d0 = q[0] * k0[0] + q[1] * k0[1] + q[2] * k0[2] + q[3] * k0[3] +
                   q[4] * k0[4] + q[5] * k0[5] + q[6] * k0[6] + q[7] * k0[7];
        d0 += __shfl_xor_sync(0xffffffffu, d0, 1);
        d0 += __shfl_xor_sync(0xffffffffu, d0, 2);
        d0 += __shfl_xor_sync(0xffffffffu, d0, 4);
        float e0 = __expf(d0 * fh);
        ssum += e0;
        acc[0] += e0 * v00.x; acc[1] += e0 * v00.y;
        acc[2] += e0 * v00.z; acc[3] += e0 * v00.w;
        acc[4] += e0 * v01.x; acc[5] += e0 * v01.y;
        acc[6] += e0 * v01.z; acc[7] += e0 * v01.w;
    }

    float inv = 1.f / (ssum + 1e-10f);
    float* op = g_comb + (size_t)node * RHD + r * HD + lo;
    *reinterpret_cast<float4*>(op) =
        make_float4(acc[0] * inv, acc[1] * inv, acc[2] * inv, acc[3] * inv);
    *reinterpret_cast<float4*>(op + 4) =
        make_float4(acc[4] * inv, acc[5] * inv, acc[6] * inv, acc[7] * inv);
}

// ---------------- 6: output projection via tf32 mma ---------------------------
// C[N,64] = comb[N,1024] @ Wo[1024,64] + bo. Block: 128 rows x 64 cols.
// 8 warps as 4(M) x 2(N): warp tile M=32, N=32. K-chunks of 64.
#define OA_STRIDE 68
#define OB_STRIDE 72
#define OUT_SMEM ((128 * OA_STRIDE + 64 * OB_STRIDE) * 4)

__global__ void __launch_bounds__(256, 2) out_mma(const float* __restrict__ Wo,
                                                  const float* __restrict__ bo,
                                                  float* __restrict__ out) {
    extern __shared__ unsigned smem[];
    unsigned* As = smem;                      // [128][68]
    unsigned* Bs = smem + 128 * OA_STRIDE;    // [64][72]

    int row0 = blockIdx.x * 128;
    int tid = threadIdx.x;
    int wid = tid >> 5, lane = tid & 31;
    int wm = (wid >> 1) * 32;   // 0,32,64,96
    int wn = (wid & 1) * 32;    // 0,32
    int g = lane >> 2, tg = lane & 3;

    float acc[2][4][4] = {};

    for (int kc = 0; kc < RHD; kc += 64) {
        // stage A: comb[row0..row0+128) x [kc..kc+64)
#pragma unroll
        for (int i = tid; i < 128 * 16; i += 256) {
            int rr = i >> 4, kq = (i & 15) << 2;
            int row = row0 + rr;
            float4 v = make_float4(0.f, 0.f, 0.f, 0.f);
            if (row < NN)
                v = *reinterpret_cast<const float4*>(g_comb + (size_t)row * RHD + kc + kq);
            unsigned* dst = As + rr * OA_STRIDE + kq;
            dst[0] = f2tf32(v.x); dst[1] = f2tf32(v.y);
            dst[2] = f2tf32(v.z); dst[3] = f2tf32(v.w);
        }
        // stage B: Wo[kc..kc+64) x [0..64)
#pragma unroll
        for (int i = tid; i < 64 * 16; i += 256) {
            int kk = i >> 4, cq = (i & 15) << 2;
            float4 v = *reinterpret_cast<const float4*>(Wo + (size_t)(kc + kk) * 64 + cq);
            unsigned* dst = Bs + kk * OB_STRIDE + cq;
            dst[0] = f2tf32(v.x); dst[1] = f2tf32(v.y);
            dst[2] = f2tf32(v.z); dst[3] = f2tf32(v.w);
        }
        __syncthreads();

#pragma unroll
        for (int kt = 0; kt < 8; kt++) {
            int k0 = kt * 8;
            unsigned a[2][4], b[4][2];
#pragma unroll
            for (int mt = 0; mt < 2; mt++) {
                int mr = wm + mt * 16;
                a[mt][0] = As[(mr + g) * OA_STRIDE + k0 + tg];
                a[mt][1] = As[(mr + g + 8) * OA_STRIDE + k0 + tg];
                a[mt][2] = As[(mr + g) * OA_STRIDE + k0 + tg + 4];
                a[mt][3] = As[(mr + g + 8) * OA_STRIDE + k0 + tg + 4];
            }
#pragma unroll
            for (int nt = 0; nt < 4; nt++) {
                int nc = wn + nt * 8;
                b[nt][0] = Bs[(k0 + tg) * OB_STRIDE + nc + g];
                b[nt][1] = Bs[(k0 + tg + 4) * OB_STRIDE + nc + g];
            }
#pragma unroll
            for (int mt = 0; mt < 2; mt++)
#pragma unroll
                for (int nt = 0; nt < 4; nt++)
                    mma_tf32(acc[mt][nt], a[mt], b[nt]);
        }
        __syncthreads();
    }

#pragma unroll
    for (int mt = 0; mt < 2; mt++) {
        int rA = row0 + wm + mt * 16 + g;
        int rB = rA + 8;
#pragma unroll
        for (int nt = 0; nt < 4; nt++) {
            int c = wn + nt * 8 + 2 * tg;
            float b0 = bo[c], b1 = bo[c + 1];
            if (rA < NN)
                *reinterpret_cast<float2*>(out + (size_t)rA * 64 + c) =
                    make_float2(acc[mt][nt][0] + b0, acc[mt][nt][1] + b1);
            if (rB < NN)
                *reinterpret_cast<float2*>(out + (size_t)rB * 64 + c) =
                    make_float2(acc[mt][nt][2] + b0, acc[mt][nt][3] + b1);
        }
    }
}

// ---------------- launch ----------------
extern "C" void kernel_launch(void* const* d_in, const int* in_sizes, int n_in,
                              void* d_out, int out_size) {
    const float* X    = (const float*)d_in[0];
    const float* infl = (const float*)d_in[1];
    const int*   esrc = (const int*)d_in[2];
    const int*   etgt = (const int*)d_in[3];
    const float* Wq   = (const float*)d_in[4];
    const float* bq   = (const float*)d_in[5];
    const float* Wk   = (const float*)d_in[6];
    const float* bk   = (const float*)d_in[7];
    const float* Wv   = (const float*)d_in[8];
    const float* bv   = (const float*)d_in[9];
    const float* sw   = (const float*)d_in[10];
    const float* Wo   = (const float*)d_in[11];
    const float* bo   = (const float*)d_in[12];
    float* out = (float*)d_out;

    cudaFuncSetAttribute(qkv_mma, cudaFuncAttributeMaxDynamicSharedMemorySize, QKV_SMEM);
    cudaFuncSetAttribute(out_mma, cudaFuncAttributeMaxDynamicSharedMemorySize, OUT_SMEM);

    zero_cnt_kernel<<<(RR * NN + 255) / 256, 256>>>();
    qkv_mma<<<dim3((NN + 127) / 128, 2, 12), 256, QKV_SMEM>>>(X, Wq, bq, Wk, bk, Wv, bv);
    hist_kernel<<<dim3((EE + 255) / 256, RR), 256>>>(esrc);
    scan_part<<<dim3(NCHUNK, RR), 1024>>>();
    scan_bsum<<<1, 128>>>();
    scan_add<<<dim3(NCHUNK, RR), 1024>>>();
    scatter_kernel<<<dim3((EE + 255) / 256, RR), 256>>>(esrc, etgt);
    attn_kernel<<<dim3((NN + 7) / 8, RR), 256>>>(infl, sw);
    out_mma<<<(NN + 127) / 128, 256, OUT_SMEM>>>(Wo, bo, out);
}